// round 1
// baseline (speedup 1.0000x reference)
#include <cuda_runtime.h>
#include <math.h>

// Problem constants
#define B_ 16
#define N_ 1024
#define L_ 120
#define C_ 1024
#define H_ 16
#define DH_ 64

// Scratch (allocation-free rule: __device__ globals)
__device__ float g_q[B_ * N_ * C_];        // 64 MB  (B,N,C)
__device__ float g_kv[B_ * L_ * 2 * C_];   // 15.7 MB (B,L,2C)  [0:C)=k, [C:2C)=v
__device__ float g_attn[B_ * N_ * C_];     // 64 MB  (B,N,C)

// ---------------------------------------------------------------------------
// SGEMM: C[m,n] = sum_k A[m,k] * B[n,k] + bias[n]
// A: (M,K) row-major, B: (N,K) row-major. M%128==0, N%128==0, K%16==0.
// 128x128 tile, BK=16, 256 threads, 8x8 per-thread microtile.
// ---------------------------------------------------------------------------
__global__ __launch_bounds__(256, 2)
void sgemm_nt_bias(const float* __restrict__ A,
                   const float* __restrict__ Bm,
                   const float* __restrict__ bias,
                   float* __restrict__ C,
                   int M, int N, int K)
{
    __shared__ float As[16][128];
    __shared__ float Bs[16][128];

    const int tid = threadIdx.x;
    const int m0 = blockIdx.y * 128;
    const int n0 = blockIdx.x * 128;
    const int tx = tid & 15;        // 0..15 -> column group
    const int ty = tid >> 4;        // 0..15 -> row group

    const int lrow = tid >> 2;          // 0..63
    const int lk4  = (tid & 3) * 4;     // 0,4,8,12

    float acc[8][8];
#pragma unroll
    for (int i = 0; i < 8; i++)
#pragma unroll
        for (int j = 0; j < 8; j++) acc[i][j] = 0.f;

    for (int k0 = 0; k0 < K; k0 += 16) {
        // Load A tile (128 rows x 16 k), transposed into As[k][m]
#pragma unroll
        for (int r = 0; r < 2; r++) {
            int row = lrow + r * 64;
            float4 v = *(const float4*)(A + (size_t)(m0 + row) * K + k0 + lk4);
            As[lk4 + 0][row] = v.x;
            As[lk4 + 1][row] = v.y;
            As[lk4 + 2][row] = v.z;
            As[lk4 + 3][row] = v.w;
        }
        // Load B tile (128 n-rows x 16 k), transposed into Bs[k][n]
#pragma unroll
        for (int r = 0; r < 2; r++) {
            int row = lrow + r * 64;
            float4 v = *(const float4*)(Bm + (size_t)(n0 + row) * K + k0 + lk4);
            Bs[lk4 + 0][row] = v.x;
            Bs[lk4 + 1][row] = v.y;
            Bs[lk4 + 2][row] = v.z;
            Bs[lk4 + 3][row] = v.w;
        }
        __syncthreads();

#pragma unroll
        for (int kk = 0; kk < 16; kk++) {
            float a[8], b[8];
            *(float4*)&a[0] = *(const float4*)&As[kk][ty * 8];
            *(float4*)&a[4] = *(const float4*)&As[kk][ty * 8 + 4];
            *(float4*)&b[0] = *(const float4*)&Bs[kk][tx * 8];
            *(float4*)&b[4] = *(const float4*)&Bs[kk][tx * 8 + 4];
#pragma unroll
            for (int i = 0; i < 8; i++)
#pragma unroll
                for (int j = 0; j < 8; j++)
                    acc[i][j] += a[i] * b[j];
        }
        __syncthreads();
    }

    // Epilogue: + bias, store
    float bv[8];
#pragma unroll
    for (int j = 0; j < 8; j++) bv[j] = bias[n0 + tx * 8 + j];

#pragma unroll
    for (int i = 0; i < 8; i++) {
        int m = m0 + ty * 8 + i;
        float* cp = C + (size_t)m * N + n0 + tx * 8;
        float4 o0, o1;
        o0.x = acc[i][0] + bv[0]; o0.y = acc[i][1] + bv[1];
        o0.z = acc[i][2] + bv[2]; o0.w = acc[i][3] + bv[3];
        o1.x = acc[i][4] + bv[4]; o1.y = acc[i][5] + bv[5];
        o1.z = acc[i][6] + bv[6]; o1.w = acc[i][7] + bv[7];
        *(float4*)(cp + 0) = o0;
        *(float4*)(cp + 4) = o1;
    }
}

// ---------------------------------------------------------------------------
// Fused masked softmax attention per (b, h):
//   scores = (Q Khᵀ) * Dh^-0.5, mask==0 -> -inf, softmax over L, out = P V
// K,V slab (120x64 each) + per-thread score rows live in dynamic smem.
// One thread == one query. 256 queries per block.
// ---------------------------------------------------------------------------
#define QT 256
#define SS_STRIDE 121   // odd stride -> conflict-free scalar score rows

__global__ __launch_bounds__(QT, 1)
void attn_kernel(const float* __restrict__ q,
                 const float* __restrict__ kv,
                 const int* __restrict__ mask,
                 float* __restrict__ out)
{
    extern __shared__ float sm[];
    float* Ks = sm;                        // 120*64
    float* Vs = Ks + L_ * DH_;             // 120*64
    float* Ss = Vs + L_ * DH_;             // QT*SS_STRIDE
    int*   mk = (int*)(Ss + QT * SS_STRIDE);

    const int b = blockIdx.z;
    const int h = blockIdx.y;
    const int n0 = blockIdx.x * QT;
    const int tid = threadIdx.x;

    // Cooperative coalesced K/V load: kv[b, l, (0|C) + h*64 + d]
    const float* kvb = kv + (size_t)b * L_ * 2 * C_;
    for (int idx = tid; idx < L_ * DH_; idx += QT) {
        int l = idx >> 6;
        int d = idx & 63;
        Ks[idx] = kvb[(size_t)l * (2 * C_) + h * DH_ + d];
        Vs[idx] = kvb[(size_t)l * (2 * C_) + C_ + h * DH_ + d];
    }
    if (tid < L_) mk[tid] = mask[b * L_ + tid];
    __syncthreads();

    const int n = n0 + tid;
    const float4* qp = (const float4*)(q + ((size_t)(b * N_ + n)) * C_ + h * DH_);
    float4 qr[16];
#pragma unroll
    for (int i = 0; i < 16; i++) qr[i] = qp[i];

    float* srow = Ss + tid * SS_STRIDE;

    // Pass 1: scores + running max
    float mx = -1e30f;
    for (int l = 0; l < L_; l++) {
        if (mk[l]) {
            const float4* kp = (const float4*)(Ks + l * DH_);
            float s0 = 0.f, s1 = 0.f, s2 = 0.f, s3 = 0.f;
#pragma unroll
            for (int i = 0; i < 16; i++) {
                float4 k4 = kp[i];
                s0 += qr[i].x * k4.x;
                s1 += qr[i].y * k4.y;
                s2 += qr[i].z * k4.z;
                s3 += qr[i].w * k4.w;
            }
            float s = ((s0 + s1) + (s2 + s3)) * 0.125f;  // Dh^-0.5 = 1/8
            srow[l] = s;
            mx = fmaxf(mx, s);
        }
    }

    // Pass 2: exponentiate + sum
    float sum = 0.f;
    for (int l = 0; l < L_; l++) {
        if (mk[l]) {
            float p = __expf(srow[l] - mx);
            srow[l] = p;
            sum += p;
        }
    }
    float inv = 1.0f / sum;

    // Pass 3: out = P V
    float4 o[16];
#pragma unroll
    for (int i = 0; i < 16; i++) o[i] = make_float4(0.f, 0.f, 0.f, 0.f);
    for (int l = 0; l < L_; l++) {
        if (mk[l]) {
            float p = srow[l];
            const float4* vp = (const float4*)(Vs + l * DH_);
#pragma unroll
            for (int i = 0; i < 16; i++) {
                float4 v4 = vp[i];
                o[i].x += p * v4.x;
                o[i].y += p * v4.y;
                o[i].z += p * v4.z;
                o[i].w += p * v4.w;
            }
        }
    }

    float4* op = (float4*)(out + ((size_t)(b * N_ + n)) * C_ + h * DH_);
#pragma unroll
    for (int i = 0; i < 16; i++) {
        o[i].x *= inv; o[i].y *= inv; o[i].z *= inv; o[i].w *= inv;
        op[i] = o[i];
    }
}

// ---------------------------------------------------------------------------
// Launcher
// ---------------------------------------------------------------------------
extern "C" void kernel_launch(void* const* d_in, const int* in_sizes, int n_in,
                              void* d_out, int out_size)
{
    const float* x    = (const float*)d_in[0];  // (16,1024,1024)
    const float* cond = (const float*)d_in[1];  // (16,120,1024)
    const int*   mask = (const int*)  d_in[2];  // (16,120)
    const float* Wq   = (const float*)d_in[3];  // (1024,1024)
    const float* bq   = (const float*)d_in[4];
    const float* Wkv  = (const float*)d_in[5];  // (2048,1024)
    const float* bkv  = (const float*)d_in[6];
    const float* Wp   = (const float*)d_in[7];  // (1024,1024)
    const float* bp   = (const float*)d_in[8];
    float* out = (float*)d_out;

    float *q_ptr, *kv_ptr, *attn_ptr;
    cudaGetSymbolAddress((void**)&q_ptr,    g_q);
    cudaGetSymbolAddress((void**)&kv_ptr,   g_kv);
    cudaGetSymbolAddress((void**)&attn_ptr, g_attn);

    const int smem_attn = (L_ * DH_ * 2 + QT * SS_STRIDE) * (int)sizeof(float)
                        + L_ * (int)sizeof(int);
    cudaFuncSetAttribute(attn_kernel,
                         cudaFuncAttributeMaxDynamicSharedMemorySize, smem_attn);

    // KV projection: (B*L=1920, 2048) = cond(1920,1024) @ Wkv^T + bkv
    {
        dim3 grid(2048 / 128, 1920 / 128);
        sgemm_nt_bias<<<grid, 256>>>(cond, Wkv, bkv, kv_ptr, 1920, 2048, 1024);
    }
    // Q projection: (B*N=16384, 1024) = x @ Wq^T + bq
    {
        dim3 grid(1024 / 128, 16384 / 128);
        sgemm_nt_bias<<<grid, 256>>>(x, Wq, bq, q_ptr, 16384, 1024, 1024);
    }
    // Fused attention
    {
        dim3 grid(N_ / QT, H_, B_);
        attn_kernel<<<grid, QT, smem_attn>>>(q_ptr, kv_ptr, mask, attn_ptr);
    }
    // Output projection: out = attn @ Wp^T + bp
    {
        dim3 grid(1024 / 128, 16384 / 128);
        sgemm_nt_bias<<<grid, 256>>>(attn_ptr, Wp, bp, out, 16384, 1024, 1024);
    }
}

// round 3
// speedup vs baseline: 2.2650x; 2.2650x over previous
#include <cuda_runtime.h>
#include <cuda_bf16.h>
#include <cstdint>
#include <cstring>

// Problem constants
#define B_ 16
#define N_ 1024
#define L_ 120
#define C_ 1024
#define H_ 16
#define DH_ 64

// Scratch (allocation-free rule: __device__ globals)
__device__ float g_q[B_ * N_ * C_];
__device__ float g_kv[B_ * L_ * 2 * C_];
__device__ float g_attn[B_ * N_ * C_];

// ---------------------------------------------------------------------------
// Tensor-core GEMM via mma.sync (bf16 split precision, fp32 accumulate)
//   C[m,n] = sum_k A[m,k] * B[n,k] + bias[n]
//   A: (M,K) row-major fp32, B: (N,K) row-major fp32.
//   Split: x = hi(bf16) + lo(bf16);  D += Ahi*Bhi + Ahi*Blo + Alo*Bhi
// Tile: BM=128, BN=128, BK=32; 256 threads (8 warps), warp tile 32x64.
// SMEM rows: 32 bf16 = 64B data @ 80B stride -> conflict-free ldmatrix.
// ---------------------------------------------------------------------------
#define BM 128
#define BN 128
#define BK 32
#define TPB 256
#define ROWB 80                         // smem row stride in bytes
#define TILE_BYTES (128 * ROWB)         // 10240 per operand tile
#define SM_AHI 0
#define SM_ALO TILE_BYTES
#define SM_BHI (2 * TILE_BYTES)
#define SM_BLO (3 * TILE_BYTES)
#define GEMM_SMEM (4 * TILE_BYTES)      // 40960 B

__device__ __forceinline__ uint32_t smem_u32(const void* p) {
    uint32_t a;
    asm("{ .reg .u64 t; cvta.to.shared.u64 t, %1; cvt.u32.u64 %0, t; }"
        : "=r"(a) : "l"(p));
    return a;
}

#define LDM4(r, addr) \
    asm volatile("ldmatrix.sync.aligned.m8n8.x4.shared.b16 {%0,%1,%2,%3}, [%4];" \
                 : "=r"((r)[0]), "=r"((r)[1]), "=r"((r)[2]), "=r"((r)[3]) \
                 : "r"(addr))

#define MMA16816(d, a, b0, b1) \
    asm volatile("mma.sync.aligned.m16n8k16.row.col.f32.bf16.bf16.f32 " \
                 "{%0,%1,%2,%3}, {%4,%5,%6,%7}, {%8,%9}, {%0,%1,%2,%3};" \
                 : "+f"((d)[0]), "+f"((d)[1]), "+f"((d)[2]), "+f"((d)[3]) \
                 : "r"((a)[0]), "r"((a)[1]), "r"((a)[2]), "r"((a)[3]), \
                   "r"(b0), "r"(b1))

__device__ __forceinline__ void split_store(uint32_t hi_addr, uint32_t lo_addr, float4 v) {
    __nv_bfloat162 h01 = __float22bfloat162_rn(make_float2(v.x, v.y));
    __nv_bfloat162 h23 = __float22bfloat162_rn(make_float2(v.z, v.w));
    float2 f01 = __bfloat1622float2(h01);
    float2 f23 = __bfloat1622float2(h23);
    __nv_bfloat162 l01 = __float22bfloat162_rn(make_float2(v.x - f01.x, v.y - f01.y));
    __nv_bfloat162 l23 = __float22bfloat162_rn(make_float2(v.z - f23.x, v.w - f23.y));
    uint32_t uh0, uh1, ul0, ul1;
    memcpy(&uh0, &h01, 4); memcpy(&uh1, &h23, 4);
    memcpy(&ul0, &l01, 4); memcpy(&ul1, &l23, 4);
    asm volatile("st.shared.v2.b32 [%0], {%1, %2};" :: "r"(hi_addr), "r"(uh0), "r"(uh1));
    asm volatile("st.shared.v2.b32 [%0], {%1, %2};" :: "r"(lo_addr), "r"(ul0), "r"(ul1));
}

__global__ __launch_bounds__(TPB, 1)
void tc_gemm_nt_bias(const float* __restrict__ A,
                     const float* __restrict__ Bm,
                     const float* __restrict__ bias,
                     float* __restrict__ C,
                     int M, int N, int K)
{
    extern __shared__ char smem_raw[];
    const uint32_t sb = smem_u32(smem_raw);

    const int tid = threadIdx.x;
    const int wid = tid >> 5;
    const int l   = tid & 31;
    const int m0 = blockIdx.y * BM;
    const int n0 = blockIdx.x * BN;
    const int wm = (wid & 3) * 32;   // warp m offset within tile
    const int wn = (wid >> 2) * 64;  // warp n offset within tile

    // cooperative-load indexing: 1024 float4 per operand per chunk, 4/thread
    const int ldRow = tid >> 3;        // 0..31 (+32 per i)
    const int ldC4  = tid & 7;         // float4 column within 32-float row

    // ldmatrix lane addresses (byte offsets into a 128x(32bf16) tile)
    const uint32_t aOff = (uint32_t)((wm + (l & 15)) * ROWB + (((l >> 4) << 3) * 2));
    const uint32_t bOff = (uint32_t)((wn + (l & 7) + ((l >> 4) << 3)) * ROWB
                                     + ((((l >> 3) & 1) << 3) * 2));

    float acc[2][8][4];
#pragma unroll
    for (int mt = 0; mt < 2; mt++)
#pragma unroll
        for (int nt = 0; nt < 8; nt++)
#pragma unroll
            for (int r = 0; r < 4; r++) acc[mt][nt][r] = 0.f;

    const int nch = K / BK;
    float4 ra[4], rb[4];

    // prefetch chunk 0
#pragma unroll
    for (int i = 0; i < 4; i++) {
        int row = ldRow + i * 32;
        ra[i] = *(const float4*)(A + (size_t)(m0 + row) * K + ldC4 * 4);
        rb[i] = *(const float4*)(Bm + (size_t)(n0 + row) * K + ldC4 * 4);
    }

    for (int c = 0; c < nch; c++) {
        // store staged chunk to smem (split hi/lo)
#pragma unroll
        for (int i = 0; i < 4; i++) {
            uint32_t so = (uint32_t)((ldRow + i * 32) * ROWB + ldC4 * 8);
            split_store(sb + SM_AHI + so, sb + SM_ALO + so, ra[i]);
            split_store(sb + SM_BHI + so, sb + SM_BLO + so, rb[i]);
        }
        __syncthreads();

        // prefetch next chunk (overlaps with compute below)
        if (c + 1 < nch) {
            const int k0 = (c + 1) * BK;
#pragma unroll
            for (int i = 0; i < 4; i++) {
                int row = ldRow + i * 32;
                ra[i] = *(const float4*)(A + (size_t)(m0 + row) * K + k0 + ldC4 * 4);
                rb[i] = *(const float4*)(Bm + (size_t)(n0 + row) * K + k0 + ldC4 * 4);
            }
        }

        // compute: 2 k16 steps x 3 split passes x (2 m-tiles x 8 n-tiles)
#pragma unroll
        for (int ks = 0; ks < 2; ks++) {
            const uint32_t kso = (uint32_t)(ks * 32);   // 16 bf16 = 32B
            uint32_t ah[2][4], al[2][4];
#pragma unroll
            for (int mt = 0; mt < 2; mt++) {
                LDM4(ah[mt], sb + SM_AHI + aOff + mt * (16 * ROWB) + kso);
                LDM4(al[mt], sb + SM_ALO + aOff + mt * (16 * ROWB) + kso);
            }
            uint32_t bh[4][4], bl[4][4];
#pragma unroll
            for (int j = 0; j < 4; j++) {
                LDM4(bh[j], sb + SM_BHI + bOff + j * (16 * ROWB) + kso);
                LDM4(bl[j], sb + SM_BLO + bOff + j * (16 * ROWB) + kso);
            }
#pragma unroll
            for (int mt = 0; mt < 2; mt++)
#pragma unroll
                for (int nt = 0; nt < 8; nt++) {
                    const int j = nt >> 1, h = (nt & 1) * 2;
                    MMA16816(acc[mt][nt], ah[mt], bh[j][h], bh[j][h + 1]);
                    MMA16816(acc[mt][nt], ah[mt], bl[j][h], bl[j][h + 1]);
                    MMA16816(acc[mt][nt], al[mt], bh[j][h], bh[j][h + 1]);
                }
        }
        __syncthreads();
    }

    // Epilogue: accum frag -> C (+bias). c0,c1: (row l/4, col (l%4)*2); c2,c3: row+8.
    const int cm = m0 + wm + (l >> 2);
    const int cn = n0 + wn + (l & 3) * 2;
#pragma unroll
    for (int mt = 0; mt < 2; mt++) {
#pragma unroll
        for (int nt = 0; nt < 8; nt++) {
            const int col = cn + nt * 8;
            const float b0 = bias[col], b1 = bias[col + 1];
            float* p0 = C + (size_t)(cm + mt * 16) * N + col;
            float* p1 = C + (size_t)(cm + mt * 16 + 8) * N + col;
            *(float2*)p0 = make_float2(acc[mt][nt][0] + b0, acc[mt][nt][1] + b1);
            *(float2*)p1 = make_float2(acc[mt][nt][2] + b0, acc[mt][nt][3] + b1);
        }
    }
}

// ---------------------------------------------------------------------------
// Fused masked softmax attention per (b, h)  [unchanged]
// ---------------------------------------------------------------------------
#define QT 256
#define SS_STRIDE 121

__global__ __launch_bounds__(QT, 1)
void attn_kernel(const float* __restrict__ q,
                 const float* __restrict__ kv,
                 const int* __restrict__ mask,
                 float* __restrict__ out)
{
    extern __shared__ float sm[];
    float* Ks = sm;
    float* Vs = Ks + L_ * DH_;
    float* Ss = Vs + L_ * DH_;
    int*   mk = (int*)(Ss + QT * SS_STRIDE);

    const int b = blockIdx.z;
    const int h = blockIdx.y;
    const int n0 = blockIdx.x * QT;
    const int tid = threadIdx.x;

    const float* kvb = kv + (size_t)b * L_ * 2 * C_;
    for (int idx = tid; idx < L_ * DH_; idx += QT) {
        int ll = idx >> 6;
        int d = idx & 63;
        Ks[idx] = kvb[(size_t)ll * (2 * C_) + h * DH_ + d];
        Vs[idx] = kvb[(size_t)ll * (2 * C_) + C_ + h * DH_ + d];
    }
    if (tid < L_) mk[tid] = mask[b * L_ + tid];
    __syncthreads();

    const int n = n0 + tid;
    const float4* qp = (const float4*)(q + ((size_t)(b * N_ + n)) * C_ + h * DH_);
    float4 qr[16];
#pragma unroll
    for (int i = 0; i < 16; i++) qr[i] = qp[i];

    float* srow = Ss + tid * SS_STRIDE;

    float mx = -1e30f;
    for (int ll = 0; ll < L_; ll++) {
        if (mk[ll]) {
            const float4* kp = (const float4*)(Ks + ll * DH_);
            float s0 = 0.f, s1 = 0.f, s2 = 0.f, s3 = 0.f;
#pragma unroll
            for (int i = 0; i < 16; i++) {
                float4 k4 = kp[i];
                s0 += qr[i].x * k4.x;
                s1 += qr[i].y * k4.y;
                s2 += qr[i].z * k4.z;
                s3 += qr[i].w * k4.w;
            }
            float s = ((s0 + s1) + (s2 + s3)) * 0.125f;
            srow[ll] = s;
            mx = fmaxf(mx, s);
        }
    }

    float sum = 0.f;
    for (int ll = 0; ll < L_; ll++) {
        if (mk[ll]) {
            float p = __expf(srow[ll] - mx);
            srow[ll] = p;
            sum += p;
        }
    }
    float inv = 1.0f / sum;

    float4 o[16];
#pragma unroll
    for (int i = 0; i < 16; i++) o[i] = make_float4(0.f, 0.f, 0.f, 0.f);
    for (int ll = 0; ll < L_; ll++) {
        if (mk[ll]) {
            float p = srow[ll];
            const float4* vp = (const float4*)(Vs + ll * DH_);
#pragma unroll
            for (int i = 0; i < 16; i++) {
                float4 v4 = vp[i];
                o[i].x += p * v4.x;
                o[i].y += p * v4.y;
                o[i].z += p * v4.z;
                o[i].w += p * v4.w;
            }
        }
    }

    float4* op = (float4*)(out + ((size_t)(b * N_ + n)) * C_ + h * DH_);
#pragma unroll
    for (int i = 0; i < 16; i++) {
        o[i].x *= inv; o[i].y *= inv; o[i].z *= inv; o[i].w *= inv;
        op[i] = o[i];
    }
}

// ---------------------------------------------------------------------------
// Launcher
// ---------------------------------------------------------------------------
extern "C" void kernel_launch(void* const* d_in, const int* in_sizes, int n_in,
                              void* d_out, int out_size)
{
    const float* x    = (const float*)d_in[0];
    const float* cond = (const float*)d_in[1];
    const int*   mask = (const int*)  d_in[2];
    const float* Wq   = (const float*)d_in[3];
    const float* bq   = (const float*)d_in[4];
    const float* Wkv  = (const float*)d_in[5];
    const float* bkv  = (const float*)d_in[6];
    const float* Wp   = (const float*)d_in[7];
    const float* bp   = (const float*)d_in[8];
    float* out = (float*)d_out;

    float *q_ptr, *kv_ptr, *attn_ptr;
    cudaGetSymbolAddress((void**)&q_ptr,    g_q);
    cudaGetSymbolAddress((void**)&kv_ptr,   g_kv);
    cudaGetSymbolAddress((void**)&attn_ptr, g_attn);

    cudaFuncSetAttribute(tc_gemm_nt_bias,
                         cudaFuncAttributeMaxDynamicSharedMemorySize, GEMM_SMEM);
    const int smem_attn = (L_ * DH_ * 2 + QT * SS_STRIDE) * (int)sizeof(float)
                        + L_ * (int)sizeof(int);
    cudaFuncSetAttribute(attn_kernel,
                         cudaFuncAttributeMaxDynamicSharedMemorySize, smem_attn);

    // KV projection: (1920, 2048) = cond(1920,1024) @ Wkv^T + bkv
    {
        dim3 grid(2048 / BN, 1920 / BM);
        tc_gemm_nt_bias<<<grid, TPB, GEMM_SMEM>>>(cond, Wkv, bkv, kv_ptr, 1920, 2048, 1024);
    }
    // Q projection: (16384, 1024) = x @ Wq^T + bq
    {
        dim3 grid(1024 / BN, 16384 / BM);
        tc_gemm_nt_bias<<<grid, TPB, GEMM_SMEM>>>(x, Wq, bq, q_ptr, 16384, 1024, 1024);
    }
    // Fused attention
    {
        dim3 grid(N_ / QT, H_, B_);
        attn_kernel<<<grid, QT, smem_attn>>>(q_ptr, kv_ptr, mask, attn_ptr);
    }
    // Output projection: out = attn @ Wp^T + bp
    {
        dim3 grid(1024 / BN, 16384 / BM);
        tc_gemm_nt_bias<<<grid, TPB, GEMM_SMEM>>>(attn_ptr, Wp, bp, out, 16384, 1024, 1024);
    }
}

// round 4
// speedup vs baseline: 2.5427x; 1.1226x over previous
#include <cuda_runtime.h>
#include <cuda_bf16.h>
#include <cstdint>
#include <cstring>

// Problem constants
#define B_ 16
#define N_ 1024
#define L_ 120
#define C_ 1024
#define H_ 16
#define DH_ 64

// Scratch (allocation-free rule: __device__ globals)
__device__ float g_q[B_ * N_ * C_];
__device__ float g_kv[B_ * L_ * 2 * C_];
__device__ float g_attn[B_ * N_ * C_];

// ---------------------------------------------------------------------------
// Common helpers
// ---------------------------------------------------------------------------
__device__ __forceinline__ uint32_t smem_u32(const void* p) {
    uint32_t a;
    asm("{ .reg .u64 t; cvta.to.shared.u64 t, %1; cvt.u32.u64 %0, t; }"
        : "=r"(a) : "l"(p));
    return a;
}

#define LDM4(r, addr) \
    asm volatile("ldmatrix.sync.aligned.m8n8.x4.shared.b16 {%0,%1,%2,%3}, [%4];" \
                 : "=r"((r)[0]), "=r"((r)[1]), "=r"((r)[2]), "=r"((r)[3]) \
                 : "r"(addr))

#define MMA16816(d, a, b0, b1) \
    asm volatile("mma.sync.aligned.m16n8k16.row.col.f32.bf16.bf16.f32 " \
                 "{%0,%1,%2,%3}, {%4,%5,%6,%7}, {%8,%9}, {%0,%1,%2,%3};" \
                 : "+f"((d)[0]), "+f"((d)[1]), "+f"((d)[2]), "+f"((d)[3]) \
                 : "r"((a)[0]), "r"((a)[1]), "r"((a)[2]), "r"((a)[3]), \
                   "r"(b0), "r"(b1))

__device__ __forceinline__ void split_store(uint32_t hi_addr, uint32_t lo_addr, float4 v) {
    __nv_bfloat162 h01 = __float22bfloat162_rn(make_float2(v.x, v.y));
    __nv_bfloat162 h23 = __float22bfloat162_rn(make_float2(v.z, v.w));
    float2 f01 = __bfloat1622float2(h01);
    float2 f23 = __bfloat1622float2(h23);
    __nv_bfloat162 l01 = __float22bfloat162_rn(make_float2(v.x - f01.x, v.y - f01.y));
    __nv_bfloat162 l23 = __float22bfloat162_rn(make_float2(v.z - f23.x, v.w - f23.y));
    uint32_t uh0, uh1, ul0, ul1;
    memcpy(&uh0, &h01, 4); memcpy(&uh1, &h23, 4);
    memcpy(&ul0, &l01, 4); memcpy(&ul1, &l23, 4);
    asm volatile("st.shared.v2.b32 [%0], {%1, %2};" :: "r"(hi_addr), "r"(uh0), "r"(uh1));
    asm volatile("st.shared.v2.b32 [%0], {%1, %2};" :: "r"(lo_addr), "r"(ul0), "r"(ul1));
}

// pack two floats to bf16x2 (hi) and return residuals
__device__ __forceinline__ uint32_t pack_hi(float a, float b, float& ra, float& rb) {
    __nv_bfloat162 h = __float22bfloat162_rn(make_float2(a, b));
    float2 f = __bfloat1622float2(h);
    ra = a - f.x; rb = b - f.y;
    uint32_t u; memcpy(&u, &h, 4); return u;
}
__device__ __forceinline__ uint32_t pack_bf(float a, float b) {
    __nv_bfloat162 h = __float22bfloat162_rn(make_float2(a, b));
    uint32_t u; memcpy(&u, &h, 4); return u;
}

// ---------------------------------------------------------------------------
// Tensor-core GEMM (split bf16, 3-pass), double-buffered smem.
//   C[m,n] = sum_k A[m,k]*B[n,k] + bias[n]
// Tile BM=128, BN=128, BK=32; 256 threads; warp tile 32x64.
// ---------------------------------------------------------------------------
#define BM 128
#define BN 128
#define BK 32
#define TPB 256
#define ROWB 80
#define TILE_BYTES (128 * ROWB)
#define SM_AHI 0
#define SM_ALO TILE_BYTES
#define SM_BHI (2 * TILE_BYTES)
#define SM_BLO (3 * TILE_BYTES)
#define GEMM_STAGE (4 * TILE_BYTES)      // 40960
#define GEMM_SMEM (2 * GEMM_STAGE)       // 81920

__global__ __launch_bounds__(TPB, 1)
void tc_gemm_nt_bias(const float* __restrict__ A,
                     const float* __restrict__ Bm,
                     const float* __restrict__ bias,
                     float* __restrict__ C,
                     int M, int N, int K)
{
    extern __shared__ char smem_raw[];
    const uint32_t sb = smem_u32(smem_raw);

    const int tid = threadIdx.x;
    const int wid = tid >> 5;
    const int l   = tid & 31;
    const int m0 = blockIdx.y * BM;
    const int n0 = blockIdx.x * BN;
    const int wm = (wid & 3) * 32;
    const int wn = (wid >> 2) * 64;

    const int ldRow = tid >> 3;
    const int ldC4  = tid & 7;

    const uint32_t aOff = (uint32_t)((wm + (l & 15)) * ROWB + ((l >> 4) << 4));
    const uint32_t bOff = (uint32_t)((wn + (l & 7) + ((l >> 4) << 3)) * ROWB
                                     + (((l >> 3) & 1) << 4));

    float acc[2][8][4];
#pragma unroll
    for (int mt = 0; mt < 2; mt++)
#pragma unroll
        for (int nt = 0; nt < 8; nt++)
#pragma unroll
            for (int r = 0; r < 4; r++) acc[mt][nt][r] = 0.f;

    const int nch = K / BK;
    float4 ra[4], rb[4];

    // prologue: chunk 0 -> regs -> stage 0
#pragma unroll
    for (int i = 0; i < 4; i++) {
        int row = ldRow + i * 32;
        ra[i] = *(const float4*)(A + (size_t)(m0 + row) * K + ldC4 * 4);
        rb[i] = *(const float4*)(Bm + (size_t)(n0 + row) * K + ldC4 * 4);
    }
#pragma unroll
    for (int i = 0; i < 4; i++) {
        uint32_t so = (uint32_t)((ldRow + i * 32) * ROWB + ldC4 * 8);
        split_store(sb + SM_AHI + so, sb + SM_ALO + so, ra[i]);
        split_store(sb + SM_BHI + so, sb + SM_BLO + so, rb[i]);
    }
    __syncthreads();

    for (int c = 0; c < nch; c++) {
        const uint32_t st = sb + (uint32_t)(c & 1) * GEMM_STAGE;

        // prefetch next chunk into regs (overlaps with MMAs below)
        if (c + 1 < nch) {
            const int k0 = (c + 1) * BK;
#pragma unroll
            for (int i = 0; i < 4; i++) {
                int row = ldRow + i * 32;
                ra[i] = *(const float4*)(A + (size_t)(m0 + row) * K + k0 + ldC4 * 4);
                rb[i] = *(const float4*)(Bm + (size_t)(n0 + row) * K + k0 + ldC4 * 4);
            }
        }

        // compute chunk c from stage st
#pragma unroll
        for (int ks = 0; ks < 2; ks++) {
            const uint32_t kso = (uint32_t)(ks * 32);
            uint32_t ah[2][4], al[2][4];
#pragma unroll
            for (int mt = 0; mt < 2; mt++) {
                LDM4(ah[mt], st + SM_AHI + aOff + mt * (16 * ROWB) + kso);
                LDM4(al[mt], st + SM_ALO + aOff + mt * (16 * ROWB) + kso);
            }
            uint32_t bh[4][4], bl[4][4];
#pragma unroll
            for (int j = 0; j < 4; j++) {
                LDM4(bh[j], st + SM_BHI + bOff + j * (16 * ROWB) + kso);
                LDM4(bl[j], st + SM_BLO + bOff + j * (16 * ROWB) + kso);
            }
#pragma unroll
            for (int mt = 0; mt < 2; mt++)
#pragma unroll
                for (int nt = 0; nt < 8; nt++) {
                    const int j = nt >> 1, h = (nt & 1) * 2;
                    MMA16816(acc[mt][nt], ah[mt], bh[j][h], bh[j][h + 1]);
                    MMA16816(acc[mt][nt], ah[mt], bl[j][h], bl[j][h + 1]);
                    MMA16816(acc[mt][nt], al[mt], bh[j][h], bh[j][h + 1]);
                }
        }

        // store next chunk into the other stage
        if (c + 1 < nch) {
            const uint32_t st2 = sb + (uint32_t)((c + 1) & 1) * GEMM_STAGE;
#pragma unroll
            for (int i = 0; i < 4; i++) {
                uint32_t so = (uint32_t)((ldRow + i * 32) * ROWB + ldC4 * 8);
                split_store(st2 + SM_AHI + so, st2 + SM_ALO + so, ra[i]);
                split_store(st2 + SM_BHI + so, st2 + SM_BLO + so, rb[i]);
            }
        }
        __syncthreads();
    }

    // Epilogue
    const int cm = m0 + wm + (l >> 2);
    const int cn = n0 + wn + (l & 3) * 2;
#pragma unroll
    for (int mt = 0; mt < 2; mt++) {
#pragma unroll
        for (int nt = 0; nt < 8; nt++) {
            const int col = cn + nt * 8;
            const float b0 = bias[col], b1 = bias[col + 1];
            float* p0 = C + (size_t)(cm + mt * 16) * N + col;
            float* p1 = C + (size_t)(cm + mt * 16 + 8) * N + col;
            *(float2*)p0 = make_float2(acc[mt][nt][0] + b0, acc[mt][nt][1] + b1);
            *(float2*)p1 = make_float2(acc[mt][nt][2] + b0, acc[mt][nt][3] + b1);
        }
    }
}

// ---------------------------------------------------------------------------
// Tensor-core fused attention per (b, h, 128-query tile).
//   S = Q K^T (split bf16, 3-pass), mask->-inf, softmax, O = P V (split, 3-pass)
// 256 threads = 8 warps, each warp owns 16 query rows.
// ---------------------------------------------------------------------------
#define AT_ROWB 144              // Q/K rows: 64 bf16 = 128B data @144B stride
#define VT_ROWB 272              // Vt rows: 128 bf16 = 256B data @272B stride
#define AQ_HI 0
#define AQ_LO 18432
#define AK_HI 36864
#define AK_LO 55296
#define AVT_HI 73728
#define AVT_LO 91136
#define AMK 108544
#define ATTN_SMEM 109056

__global__ __launch_bounds__(256, 1)
void attn_tc_kernel(const float* __restrict__ q,
                    const float* __restrict__ kv,
                    const int* __restrict__ mask,
                    float* __restrict__ out)
{
    extern __shared__ char smem_raw[];
    const uint32_t sb = smem_u32(smem_raw);
    const int tid = threadIdx.x, wid = tid >> 5, l = tid & 31;
    const int b = blockIdx.z, h = blockIdx.y, n0 = blockIdx.x * 128;
    const int wm = wid * 16;

    // ---- Load Q tile (128x64), split to bf16 hi/lo
    const float* qbase = q + ((size_t)(b * N_ + n0)) * C_ + h * DH_;
#pragma unroll
    for (int i = 0; i < 8; i++) {
        int f = i * 256 + tid;
        int row = f >> 4, c4 = f & 15;
        float4 v = *(const float4*)(qbase + (size_t)row * C_ + c4 * 4);
        uint32_t so = (uint32_t)(row * AT_ROWB + c4 * 8);
        split_store(sb + AQ_HI + so, sb + AQ_LO + so, v);
    }
    // ---- Load K (120x64, zero-pad to 128 rows)
    const float* kvb = kv + (size_t)b * L_ * 2 * C_;
#pragma unroll
    for (int i = 0; i < 8; i++) {
        int f = i * 256 + tid;
        int row = f >> 4, c4 = f & 15;
        float4 v = make_float4(0.f, 0.f, 0.f, 0.f);
        if (row < L_) v = *(const float4*)(kvb + (size_t)row * (2 * C_) + h * DH_ + c4 * 4);
        uint32_t so = (uint32_t)(row * AT_ROWB + c4 * 8);
        split_store(sb + AK_HI + so, sb + AK_LO + so, v);
    }
    // ---- Load V transposed: Vt[dh=64][L padded to 128]
#pragma unroll
    for (int i = 0; i < 8; i++) {
        int f = i * 256 + tid;
        int row = f >> 4, c4 = f & 15;          // row = L index
        float4 v = make_float4(0.f, 0.f, 0.f, 0.f);
        if (row < L_) v = *(const float4*)(kvb + (size_t)row * (2 * C_) + C_ + h * DH_ + c4 * 4);
        float vv[4] = {v.x, v.y, v.z, v.w};
#pragma unroll
        for (int j = 0; j < 4; j++) {
            __nv_bfloat16 hi = __float2bfloat16(vv[j]);
            float hif = __bfloat162float(hi);
            __nv_bfloat16 lo = __float2bfloat16(vv[j] - hif);
            uint16_t uh, ul; memcpy(&uh, &hi, 2); memcpy(&ul, &lo, 2);
            uint32_t off = (uint32_t)((c4 * 4 + j) * VT_ROWB + row * 2);
            asm volatile("st.shared.b16 [%0], %1;" :: "r"(sb + AVT_HI + off), "h"(uh));
            asm volatile("st.shared.b16 [%0], %1;" :: "r"(sb + AVT_LO + off), "h"(ul));
        }
    }
    // ---- mask (pad cols >= L_ -> 0)
    if (tid < 128) {
        int m = (tid < L_) ? mask[b * L_ + tid] : 0;
        asm volatile("st.shared.b32 [%0], %1;" :: "r"(sb + AMK + tid * 4), "r"(m));
    }
    __syncthreads();

    // ---- S = Q K^T  (sacc[nt] = 16x8 accumulator tile, nt over 128 key cols)
    float sacc[16][4];
#pragma unroll
    for (int nt = 0; nt < 16; nt++)
#pragma unroll
        for (int r = 0; r < 4; r++) sacc[nt][r] = 0.f;

    const uint32_t aOff = (uint32_t)((wm + (l & 15)) * AT_ROWB + ((l >> 4) << 4));
    const uint32_t bOffK = (uint32_t)(((l & 7) + ((l >> 4) << 3)) * AT_ROWB
                                      + (((l >> 3) & 1) << 4));
#pragma unroll
    for (int ks = 0; ks < 4; ks++) {
        const uint32_t kso = (uint32_t)(ks * 32);
        uint32_t ah[4], al[4];
        LDM4(ah, sb + AQ_HI + aOff + kso);
        LDM4(al, sb + AQ_LO + aOff + kso);
#pragma unroll
        for (int j = 0; j < 8; j++) {
            uint32_t bh[4], bl[4];
            LDM4(bh, sb + AK_HI + bOffK + j * (16 * AT_ROWB) + kso);
            LDM4(bl, sb + AK_LO + bOffK + j * (16 * AT_ROWB) + kso);
            MMA16816(sacc[2 * j],     ah, bh[0], bh[1]);
            MMA16816(sacc[2 * j],     ah, bl[0], bl[1]);
            MMA16816(sacc[2 * j],     al, bh[0], bh[1]);
            MMA16816(sacc[2 * j + 1], ah, bh[2], bh[3]);
            MMA16816(sacc[2 * j + 1], ah, bl[2], bl[3]);
            MMA16816(sacc[2 * j + 1], al, bh[2], bh[3]);
        }
    }

    // ---- mask + softmax (rows: r0 = wm + l/4, r1 = r0+8; thread cols: nt*8+(l&3)*2,+1)
    const int c0 = (l & 3) * 2;
    float mx0 = -1e30f, mx1 = -1e30f;
#pragma unroll
    for (int nt = 0; nt < 16; nt++) {
        int col = nt * 8 + c0;
        int m0_, m1_;
        asm volatile("ld.shared.b32 %0, [%1];" : "=r"(m0_) : "r"(sb + AMK + col * 4));
        asm volatile("ld.shared.b32 %0, [%1];" : "=r"(m1_) : "r"(sb + AMK + (col + 1) * 4));
        if (!m0_) { sacc[nt][0] = -1e30f; sacc[nt][2] = -1e30f; }
        if (!m1_) { sacc[nt][1] = -1e30f; sacc[nt][3] = -1e30f; }
        mx0 = fmaxf(mx0, fmaxf(sacc[nt][0], sacc[nt][1]));
        mx1 = fmaxf(mx1, fmaxf(sacc[nt][2], sacc[nt][3]));
    }
    mx0 = fmaxf(mx0, __shfl_xor_sync(0xFFFFFFFFu, mx0, 1));
    mx0 = fmaxf(mx0, __shfl_xor_sync(0xFFFFFFFFu, mx0, 2));
    mx1 = fmaxf(mx1, __shfl_xor_sync(0xFFFFFFFFu, mx1, 1));
    mx1 = fmaxf(mx1, __shfl_xor_sync(0xFFFFFFFFu, mx1, 2));

    const float cexp = 0.125f * 1.4426950408889634f;   // scale * log2(e)
    float sum0 = 0.f, sum1 = 0.f;
#pragma unroll
    for (int nt = 0; nt < 16; nt++) {
        float p0 = exp2f((sacc[nt][0] - mx0) * cexp);
        float p1 = exp2f((sacc[nt][1] - mx0) * cexp);
        float p2 = exp2f((sacc[nt][2] - mx1) * cexp);
        float p3 = exp2f((sacc[nt][3] - mx1) * cexp);
        sacc[nt][0] = p0; sacc[nt][1] = p1; sacc[nt][2] = p2; sacc[nt][3] = p3;
        sum0 += p0 + p1; sum1 += p2 + p3;
    }
    sum0 += __shfl_xor_sync(0xFFFFFFFFu, sum0, 1);
    sum0 += __shfl_xor_sync(0xFFFFFFFFu, sum0, 2);
    sum1 += __shfl_xor_sync(0xFFFFFFFFu, sum1, 1);
    sum1 += __shfl_xor_sync(0xFFFFFFFFu, sum1, 2);
    const float inv0 = 1.0f / sum0, inv1 = 1.0f / sum1;

    // ---- O = P V  (A-frags packed directly from sacc; split hi/lo)
    float oacc[8][4];
#pragma unroll
    for (int nt = 0; nt < 8; nt++)
#pragma unroll
        for (int r = 0; r < 4; r++) oacc[nt][r] = 0.f;

    const uint32_t bOffV = (uint32_t)(((l & 7) + ((l >> 4) << 3)) * VT_ROWB
                                      + (((l >> 3) & 1) << 4));
#pragma unroll
    for (int j = 0; j < 8; j++) {
        uint32_t ph[4], pl[4];
        float r0, r1;
        ph[0] = pack_hi(sacc[2 * j][0],     sacc[2 * j][1],     r0, r1); pl[0] = pack_bf(r0, r1);
        ph[1] = pack_hi(sacc[2 * j][2],     sacc[2 * j][3],     r0, r1); pl[1] = pack_bf(r0, r1);
        ph[2] = pack_hi(sacc[2 * j + 1][0], sacc[2 * j + 1][1], r0, r1); pl[2] = pack_bf(r0, r1);
        ph[3] = pack_hi(sacc[2 * j + 1][2], sacc[2 * j + 1][3], r0, r1); pl[3] = pack_bf(r0, r1);
        const uint32_t kso = (uint32_t)(j * 32);
#pragma unroll
        for (int jj = 0; jj < 4; jj++) {
            uint32_t vh[4], vl[4];
            LDM4(vh, sb + AVT_HI + bOffV + jj * (16 * VT_ROWB) + kso);
            LDM4(vl, sb + AVT_LO + bOffV + jj * (16 * VT_ROWB) + kso);
            MMA16816(oacc[2 * jj],     ph, vh[0], vh[1]);
            MMA16816(oacc[2 * jj],     ph, vl[0], vl[1]);
            MMA16816(oacc[2 * jj],     pl, vh[0], vh[1]);
            MMA16816(oacc[2 * jj + 1], ph, vh[2], vh[3]);
            MMA16816(oacc[2 * jj + 1], ph, vl[2], vl[3]);
            MMA16816(oacc[2 * jj + 1], pl, vh[2], vh[3]);
        }
    }

    // ---- epilogue: normalize + store
    const int grow = l >> 2;
    const int row0 = n0 + wm + grow, row1 = row0 + 8;
    float* ob = out + ((size_t)b * N_) * C_ + h * DH_;
#pragma unroll
    for (int nt = 0; nt < 8; nt++) {
        int col = nt * 8 + c0;
        *(float2*)(ob + (size_t)row0 * C_ + col) =
            make_float2(oacc[nt][0] * inv0, oacc[nt][1] * inv0);
        *(float2*)(ob + (size_t)row1 * C_ + col) =
            make_float2(oacc[nt][2] * inv1, oacc[nt][3] * inv1);
    }
}

// ---------------------------------------------------------------------------
// Launcher
// ---------------------------------------------------------------------------
extern "C" void kernel_launch(void* const* d_in, const int* in_sizes, int n_in,
                              void* d_out, int out_size)
{
    const float* x    = (const float*)d_in[0];
    const float* cond = (const float*)d_in[1];
    const int*   mask = (const int*)  d_in[2];
    const float* Wq   = (const float*)d_in[3];
    const float* bq   = (const float*)d_in[4];
    const float* Wkv  = (const float*)d_in[5];
    const float* bkv  = (const float*)d_in[6];
    const float* Wp   = (const float*)d_in[7];
    const float* bp   = (const float*)d_in[8];
    float* out = (float*)d_out;

    float *q_ptr, *kv_ptr, *attn_ptr;
    cudaGetSymbolAddress((void**)&q_ptr,    g_q);
    cudaGetSymbolAddress((void**)&kv_ptr,   g_kv);
    cudaGetSymbolAddress((void**)&attn_ptr, g_attn);

    cudaFuncSetAttribute(tc_gemm_nt_bias,
                         cudaFuncAttributeMaxDynamicSharedMemorySize, GEMM_SMEM);
    cudaFuncSetAttribute(attn_tc_kernel,
                         cudaFuncAttributeMaxDynamicSharedMemorySize, ATTN_SMEM);

    // KV projection: (1920, 2048) = cond(1920,1024) @ Wkv^T + bkv
    {
        dim3 grid(2048 / BN, 1920 / BM);
        tc_gemm_nt_bias<<<grid, TPB, GEMM_SMEM>>>(cond, Wkv, bkv, kv_ptr, 1920, 2048, 1024);
    }
    // Q projection: (16384, 1024) = x @ Wq^T + bq
    {
        dim3 grid(1024 / BN, 16384 / BM);
        tc_gemm_nt_bias<<<grid, TPB, GEMM_SMEM>>>(x, Wq, bq, q_ptr, 16384, 1024, 1024);
    }
    // Fused tensor-core attention
    {
        dim3 grid(N_ / 128, H_, B_);
        attn_tc_kernel<<<grid, 256, ATTN_SMEM>>>(q_ptr, kv_ptr, mask, attn_ptr);
    }
    // Output projection: out = attn @ Wp^T + bp
    {
        dim3 grid(1024 / BN, 16384 / BM);
        tc_gemm_nt_bias<<<grid, TPB, GEMM_SMEM>>>(attn_ptr, Wp, bp, out, 16384, 1024, 1024);
    }
}